// round 1
// baseline (speedup 1.0000x reference)
#include <cuda_runtime.h>
#include <math.h>

#define Bsz 8
#define Sq  512
#define Dm  512
#define Hh  8
#define DK  64
#define FF  2048
#define MTOK (Bsz*Sq)   // 4096
#define NCPT 1000

// ---------------- scratch (device globals; no allocation) ----------------
__device__ float g_x0[MTOK*Dm];
__device__ float g_y [MTOK*Dm];
__device__ float g_x [MTOK*Dm];
__device__ float g_Q [MTOK*Dm];
__device__ float g_K [MTOK*Dm];
__device__ float g_V [MTOK*Dm];
__device__ float g_A [MTOK*Dm];
__device__ float g_O [MTOK*Dm];
__device__ float g_T1[MTOK*Dm];
__device__ float g_Hf[MTOK*FF];
__device__ float g_Cc[MTOK*2*Dm];
__device__ float g_M1[MTOK*512];
__device__ float g_M2[MTOK*1024];

// ---------------- embed ----------------
__global__ void embed_kernel(const int* __restrict__ c_data, const int* __restrict__ ca_data,
                             const float* __restrict__ c_emb, const float* __restrict__ ca_emb,
                             float* __restrict__ x0, float* __restrict__ y, float* __restrict__ x)
{
    int r = blockIdx.x;
    int c = c_data[r];
    int resp = (ca_data[r] - c) / NCPT;
    const float* er = c_emb + (size_t)c * Dm;
    const float* ar = ca_emb + (size_t)resp * Dm;
    for (int j = threadIdx.x; j < Dm; j += blockDim.x) {
        float v = er[j];
        x0[(size_t)r*Dm + j] = v;
        x [(size_t)r*Dm + j] = v;
        y [(size_t)r*Dm + j] = v + ar[j];
    }
}

// ---------------- generic tiled GEMM: C = A[MxK] @ W[KxN] + bias, opt relu --------
__global__ __launch_bounds__(256)
void gemm_kernel(const float* __restrict__ A, const float* __restrict__ W,
                 const float* __restrict__ bias, float* __restrict__ C,
                 int M, int N, int K, int relu)
{
    __shared__ float As[16][64];
    __shared__ float Ws[16][64];
    int bx = blockIdx.x;   // n tile
    int by = blockIdx.y;   // m tile
    int tid = threadIdx.x;
    int tx = tid & 15, ty = tid >> 4;
    int row0 = by * 64, col0 = bx * 64;
    const bool fullN = (col0 + 64 <= N);
    int lam = tid >> 2;            // 0..63
    int lak = (tid & 3) * 4;       // k offset for A load
    int lwk = tid >> 4;            // 0..15
    int lwn = (tid & 15) * 4;      // n offset for W load

    float acc[4][4];
#pragma unroll
    for (int i = 0; i < 4; i++)
#pragma unroll
        for (int j = 0; j < 4; j++) acc[i][j] = 0.f;

    for (int k0 = 0; k0 < K; k0 += 16) {
        float4 a4 = *(const float4*)&A[(size_t)(row0 + lam) * K + k0 + lak];
        As[lak+0][lam] = a4.x; As[lak+1][lam] = a4.y;
        As[lak+2][lam] = a4.z; As[lak+3][lam] = a4.w;
        if (fullN) {
            float4 w4 = *(const float4*)&W[(size_t)(k0 + lwk) * N + col0 + lwn];
            Ws[lwk][lwn+0] = w4.x; Ws[lwk][lwn+1] = w4.y;
            Ws[lwk][lwn+2] = w4.z; Ws[lwk][lwn+3] = w4.w;
        } else {
#pragma unroll
            for (int t = 0; t < 4; t++) {
                int cc = col0 + lwn + t;
                Ws[lwk][lwn+t] = (cc < N) ? W[(size_t)(k0 + lwk) * N + cc] : 0.f;
            }
        }
        __syncthreads();
#pragma unroll
        for (int kk = 0; kk < 16; kk++) {
            float a[4], b[4];
#pragma unroll
            for (int i = 0; i < 4; i++) a[i] = As[kk][ty*4 + i];
#pragma unroll
            for (int j = 0; j < 4; j++) b[j] = Ws[kk][tx*4 + j];
#pragma unroll
            for (int i = 0; i < 4; i++)
#pragma unroll
                for (int j = 0; j < 4; j++) acc[i][j] = fmaf(a[i], b[j], acc[i][j]);
        }
        __syncthreads();
    }
#pragma unroll
    for (int i = 0; i < 4; i++) {
        int r = row0 + ty*4 + i;
#pragma unroll
        for (int j = 0; j < 4; j++) {
            int cc = col0 + tx*4 + j;
            if (cc < N) {
                float v = acc[i][j] + bias[cc];
                if (relu) v = fmaxf(v, 0.f);
                C[(size_t)r * N + cc] = v;
            }
        }
    }
}

// ---------------- block reduce helpers (256 threads) ----------------
__device__ __forceinline__ float brmax(float v, float* red) {
    int tid = threadIdx.x;
    red[tid] = v; __syncthreads();
#pragma unroll
    for (int s = 128; s > 0; s >>= 1) {
        if (tid < s) red[tid] = fmaxf(red[tid], red[tid + s]);
        __syncthreads();
    }
    float r = red[0]; __syncthreads(); return r;
}
__device__ __forceinline__ float brsum(float v, float* red) {
    int tid = threadIdx.x;
    red[tid] = v; __syncthreads();
#pragma unroll
    for (int s = 128; s > 0; s >>= 1) {
        if (tid < s) red[tid] += red[tid + s];
        __syncthreads();
    }
    float r = red[0]; __syncthreads(); return r;
}

// ---------------- fused distance-decay attention ----------------
// one CTA per (query row i, b*H+h). 256 threads.
__global__ __launch_bounds__(256)
void attn_kernel(const float* __restrict__ Q, const float* __restrict__ Kp,
                 const float* __restrict__ V, float* __restrict__ O,
                 const float* __restrict__ gammas, int layer, int strict, int zero_pad)
{
    __shared__ float qs[DK];
    __shared__ float sc[Sq];
    __shared__ float pa[Sq];
    __shared__ float red[256];

    int i  = blockIdx.x;
    int bh = blockIdx.y;
    int b = bh >> 3, h = bh & 7;
    int tid = threadIdx.x;
    float* Orow = O + ((size_t)(b*Sq + i)) * Dm + h*DK;
    int kmax = i - strict;
    if (kmax < 0) {                       // degenerate (zero_pad row 0)
        if (tid < DK) Orow[tid] = 0.f;
        return;
    }
    if (tid < DK) qs[tid] = Q[((size_t)(b*Sq + i)) * Dm + h*DK + tid];
    __syncthreads();

    const float* Kb = Kp + ((size_t)b*Sq) * Dm + h*DK;
    const float* Vb = V  + ((size_t)b*Sq) * Dm + h*DK;

    // scores
    for (int k = tid; k < Sq; k += 256) {
        float s = -3e38f;
        if (k <= kmax) {
            const float* kr = Kb + (size_t)k * Dm;
            float a = 0.f;
#pragma unroll
            for (int d = 0; d < DK; d += 4) {
                float4 kv = *(const float4*)(kr + d);
                a = fmaf(qs[d], kv.x, fmaf(qs[d+1], kv.y,
                    fmaf(qs[d+2], kv.z, fmaf(qs[d+3], kv.w, a))));
            }
            s = a * 0.125f;
        }
        sc[k] = s;
    }
    __syncthreads();

    // softmax #1 -> p
    float lm = -3e38f;
    for (int k = tid; k < Sq; k += 256) if (k <= kmax) lm = fmaxf(lm, sc[k]);
    float m1 = brmax(lm, red);
    float ls = 0.f;
    for (int k = tid; k < Sq; k += 256) {
        float p = (k <= kmax) ? expf(sc[k] - m1) : 0.f;
        pa[k] = p; ls += p;
    }
    float inv1 = 1.f / brsum(ls, red);
    for (int k = tid; k < Sq; k += 256) pa[k] *= inv1;
    __syncthreads();

    // inclusive cumsum of p (Hillis-Steele, 512 elems / 256 threads)
    for (int off = 1; off < Sq; off <<= 1) {
        int i1 = tid + 256;
        float a0 = (tid >= off) ? pa[tid - off] : 0.f;
        float a1 = (i1  >= off) ? pa[i1  - off] : 0.f;
        __syncthreads();
        pa[tid] += a0; pa[i1] += a1;
        __syncthreads();
    }
    float total = pa[Sq - 1];

    float gm = gammas[layer * Hh + h];
    float sp = (gm > 20.f) ? gm : log1pf(expf(gm));
    float gamma = -sp;

    // distance-decay reweighted scores
    for (int k = tid; k < Sq; k += 256) {
        if (k <= kmax) {
            float suf  = total - pa[k];
            float pos  = (float)(i - k);
            float dist = sqrtf(fmaxf(suf * pos, 0.f));
            float te   = expf(dist * gamma);
            te = fminf(fmaxf(te, 1e-5f), 1e5f);
            sc[k] = sc[k] * te;
        }
    }
    __syncthreads();

    // softmax #2 -> attn
    lm = -3e38f;
    for (int k = tid; k < Sq; k += 256) if (k <= kmax) lm = fmaxf(lm, sc[k]);
    float m2 = brmax(lm, red);
    ls = 0.f;
    for (int k = tid; k < Sq; k += 256) {
        float p = (k <= kmax) ? expf(sc[k] - m2) : 0.f;
        pa[k] = p; ls += p;
    }
    float inv2 = 1.f / brsum(ls, red);
    for (int k = tid; k < Sq; k += 256) pa[k] *= inv2;
    __syncthreads();

    // out = attn @ V : 4 groups of 64 threads, group g takes k ≡ g (mod 4)
    int g = tid >> 6, d = tid & 63;
    float acc = 0.f;
    for (int k = g; k <= kmax; k += 4)
        acc = fmaf(pa[k], Vb[(size_t)k * Dm + d], acc);
    red[tid] = acc;
    __syncthreads();
    if (g == 0) {
        float v = red[d] + red[64 + d] + red[128 + d] + red[192 + d];
        Orow[d] = (zero_pad && i == 0) ? 0.f : v;
    }
}

// ---------------- residual + LayerNorm: out = LN(A + B) ----------------
__global__ void ln_add_kernel(const float* __restrict__ A, const float* __restrict__ Bv,
                              const float* __restrict__ sc, const float* __restrict__ bi,
                              float* __restrict__ out)
{
    int r = blockIdx.x, tid = threadIdx.x;   // 128 threads, 4 elems each
    const float* a  = A  + (size_t)r * Dm;
    const float* bq = Bv + (size_t)r * Dm;
    float v[4];
    float s = 0.f, s2 = 0.f;
#pragma unroll
    for (int j = 0; j < 4; j++) {
        int c = tid + j * 128;
        float t = a[c] + bq[c];
        v[j] = t; s += t; s2 += t * t;
    }
    __shared__ float rs[4], rs2[4];
#pragma unroll
    for (int o = 16; o > 0; o >>= 1) {
        s  += __shfl_down_sync(0xffffffffu, s,  o);
        s2 += __shfl_down_sync(0xffffffffu, s2, o);
    }
    int w = tid >> 5, l = tid & 31;
    if (l == 0) { rs[w] = s; rs2[w] = s2; }
    __syncthreads();
    float ss  = rs[0] + rs[1] + rs[2] + rs[3];
    float ss2 = rs2[0] + rs2[1] + rs2[2] + rs2[3];
    float mean = ss / 512.f;
    float var  = ss2 / 512.f - mean * mean;
    float rstd = rsqrtf(var + 1e-5f);
#pragma unroll
    for (int j = 0; j < 4; j++) {
        int c = tid + j * 128;
        out[(size_t)r * Dm + c] = (v[j] - mean) * rstd * sc[c] + bi[c];
    }
}

// ---------------- concat [x, x0] ----------------
__global__ void concat_kernel(const float* __restrict__ x, const float* __restrict__ x0,
                              float* __restrict__ out)
{
    int r = blockIdx.x;
    for (int j = threadIdx.x; j < 2 * Dm; j += blockDim.x)
        out[(size_t)r * 2 * Dm + j] = (j < Dm) ? x[(size_t)r*Dm + j]
                                               : x0[(size_t)r*Dm + j - Dm];
}

// ---------------- host ----------------
static inline void gemm(const float* A, const float* W, const float* bias,
                        float* C, int M, int N, int K, int relu)
{
    dim3 grid((N + 63) / 64, M / 64);
    gemm_kernel<<<grid, 256>>>(A, W, bias, C, M, N, K, relu);
}

extern "C" void kernel_launch(void* const* d_in, const int* in_sizes, int n_in,
                              void* d_out, int out_size)
{
    const int*   c_data  = (const int*)  d_in[0];
    const int*   ca_data = (const int*)  d_in[1];
    const float* c_emb   = (const float*)d_in[2];
    const float* ca_emb  = (const float*)d_in[3];
    const float* Wk      = (const float*)d_in[4];
    const float* bk      = (const float*)d_in[5];
    const float* Wv      = (const float*)d_in[6];
    const float* bv      = (const float*)d_in[7];
    const float* Wo      = (const float*)d_in[8];
    const float* bo      = (const float*)d_in[9];
    const float* gammas  = (const float*)d_in[10];
    const float* ln1s    = (const float*)d_in[11];
    const float* ln1b    = (const float*)d_in[12];
    const float* W1      = (const float*)d_in[13];
    const float* b1      = (const float*)d_in[14];
    const float* W2      = (const float*)d_in[15];
    const float* b2      = (const float*)d_in[16];
    const float* ln2s    = (const float*)d_in[17];
    const float* ln2b    = (const float*)d_in[18];
    const float* oW0     = (const float*)d_in[19];
    const float* ob0     = (const float*)d_in[20];
    const float* oW1     = (const float*)d_in[21];
    const float* ob1     = (const float*)d_in[22];
    const float* oW2     = (const float*)d_in[23];
    const float* ob2     = (const float*)d_in[24];
    float* out = (float*)d_out;

    float *x0, *y, *x, *Qb, *Kb, *Vb, *Ab, *Ob, *T1, *Hf, *Cc, *M1, *M2;
    cudaGetSymbolAddress((void**)&x0, g_x0);
    cudaGetSymbolAddress((void**)&y,  g_y);
    cudaGetSymbolAddress((void**)&x,  g_x);
    cudaGetSymbolAddress((void**)&Qb, g_Q);
    cudaGetSymbolAddress((void**)&Kb, g_K);
    cudaGetSymbolAddress((void**)&Vb, g_V);
    cudaGetSymbolAddress((void**)&Ab, g_A);
    cudaGetSymbolAddress((void**)&Ob, g_O);
    cudaGetSymbolAddress((void**)&T1, g_T1);
    cudaGetSymbolAddress((void**)&Hf, g_Hf);
    cudaGetSymbolAddress((void**)&Cc, g_Cc);
    cudaGetSymbolAddress((void**)&M1, g_M1);
    cudaGetSymbolAddress((void**)&M2, g_M2);

    embed_kernel<<<MTOK, 128>>>(c_data, ca_data, c_emb, ca_emb, x0, y, x);

    for (int li = 0; li < 6; li++) {
        int strict, zp, ap;
        float* qio; const float *kin, *vin;
        if (li < 2)            { strict = 0; zp = 0; ap = 1; qio = y; kin = x0; vin = y; }
        else {
            int j = li - 2;
            if ((j & 1) == 0)  { strict = 0; zp = 0; ap = 0; qio = x; kin = x;  vin = x; }
            else               { strict = 1; zp = 1; ap = 1; qio = x; kin = x;  vin = y; }
        }
        const float* Wk_i = Wk + (size_t)li * Dm * Dm;  const float* bk_i = bk + li * Dm;
        const float* Wv_i = Wv + (size_t)li * Dm * Dm;  const float* bv_i = bv + li * Dm;
        const float* Wo_i = Wo + (size_t)li * Dm * Dm;  const float* bo_i = bo + li * Dm;

        gemm(qio, Wk_i, bk_i, Qb, MTOK, Dm, Dm, 0);
        const float* Kuse;
        if (kin == qio) Kuse = Qb;
        else { gemm(kin, Wk_i, bk_i, Kb, MTOK, Dm, Dm, 0); Kuse = Kb; }
        gemm(vin, Wv_i, bv_i, Vb, MTOK, Dm, Dm, 0);

        attn_kernel<<<dim3(Sq, Bsz * Hh), 256>>>(Qb, Kuse, Vb, Ab, gammas, li, strict, zp);

        gemm(Ab, Wo_i, bo_i, Ob, MTOK, Dm, Dm, 0);
        ln_add_kernel<<<MTOK, 128>>>(qio, Ob, ln1s + li*Dm, ln1b + li*Dm, ap ? T1 : qio);
        if (ap) {
            gemm(T1, W1 + (size_t)li * Dm * FF, b1 + li * FF, Hf, MTOK, FF, Dm, 1);
            gemm(Hf, W2 + (size_t)li * FF * Dm, b2 + li * Dm, Ob, MTOK, Dm, FF, 0);
            ln_add_kernel<<<MTOK, 128>>>(T1, Ob, ln2s + li*Dm, ln2b + li*Dm, qio);
        }
    }

    concat_kernel<<<MTOK, 256>>>(x, x0, Cc);
    gemm(Cc, oW0, ob0, M1, MTOK, 512,  2 * Dm, 1);
    gemm(M1, oW1, ob1, M2, MTOK, 1024, 512,    1);
    gemm(M2, oW2, ob2, out, MTOK, NCPT, 1024,  0);
}

// round 2
// speedup vs baseline: 1.8991x; 1.8991x over previous
#include <cuda_runtime.h>
#include <math.h>

#define Bsz 8
#define Sq  512
#define Dm  512
#define Hh  8
#define DK  64
#define FF  2048
#define MTOK (Bsz*Sq)   // 4096
#define NCPT 1000
#define NBH (Bsz*Hh)    // 64

// ---------------- scratch (device globals; no allocation) ----------------
__device__ float g_x0[MTOK*Dm];
__device__ float g_y [MTOK*Dm];
__device__ float g_x [MTOK*Dm];
__device__ float g_Q [MTOK*Dm];
__device__ float g_K [MTOK*Dm];
__device__ float g_V [MTOK*Dm];
__device__ float g_A [MTOK*Dm];
__device__ float g_O [MTOK*Dm];
__device__ float g_T1[MTOK*Dm];
__device__ float g_Hf[MTOK*FF];
__device__ float g_Cc[MTOK*2*Dm];
__device__ float g_M1[MTOK*512];
__device__ float g_M2[MTOK*1024];
__device__ float g_S [NBH*Sq*Sq];   // 64 MB score/attn-weight scratch

// ---------------- embed ----------------
__global__ void embed_kernel(const int* __restrict__ c_data, const int* __restrict__ ca_data,
                             const float* __restrict__ c_emb, const float* __restrict__ ca_emb,
                             float* __restrict__ x0, float* __restrict__ y, float* __restrict__ x)
{
    int r = blockIdx.x;
    int c = c_data[r];
    int resp = (ca_data[r] - c) / NCPT;
    const float* er = c_emb + (size_t)c * Dm;
    const float* ar = ca_emb + (size_t)resp * Dm;
    for (int j = threadIdx.x; j < Dm; j += blockDim.x) {
        float v = er[j];
        x0[(size_t)r*Dm + j] = v;
        x [(size_t)r*Dm + j] = v;
        y [(size_t)r*Dm + j] = v + ar[j];
    }
}

// ---------------- 128x128x16 double-buffered GEMM ----------------
__device__ __forceinline__ void ldA8(const float* Ap, int koff, float* r) {
    float4 a0 = *(const float4*)(Ap + koff);
    float4 a1 = *(const float4*)(Ap + koff + 4);
    r[0]=a0.x; r[1]=a0.y; r[2]=a0.z; r[3]=a0.w;
    r[4]=a1.x; r[5]=a1.y; r[6]=a1.z; r[7]=a1.w;
}
__device__ __forceinline__ void ldB8(const float* W, int N, int krow, int col, bool full, float* r) {
    const float* p = W + (size_t)krow * N + col;
    if (full) {
        float4 b0 = *(const float4*)p;
        float4 b1 = *(const float4*)(p + 4);
        r[0]=b0.x; r[1]=b0.y; r[2]=b0.z; r[3]=b0.w;
        r[4]=b1.x; r[5]=b1.y; r[6]=b1.z; r[7]=b1.w;
    } else {
#pragma unroll
        for (int j = 0; j < 8; j++) r[j] = (col + j < N) ? p[j] : 0.f;
    }
}

__global__ __launch_bounds__(256)
void gemm128(const float* __restrict__ A, const float* __restrict__ W,
             const float* __restrict__ bias, float* __restrict__ C,
             int M, int N, int K, int relu)
{
    __shared__ float As[2][16][128];
    __shared__ float Bs[2][16][128];
    int tid = threadIdx.x;
    int row0 = blockIdx.y * 128, col0 = blockIdx.x * 128;
    int arow = tid >> 1, akc = (tid & 1) * 8;
    int bkr = tid >> 4, bcol = (tid & 15) * 8;
    int tx = tid & 15, ty = tid >> 4;
    const float* Ap = A + (size_t)(row0 + arow) * K + akc;
    int bcolg = col0 + bcol;
    bool bfull = (bcolg + 8 <= N);

    float acc[8][8];
#pragma unroll
    for (int i = 0; i < 8; i++)
#pragma unroll
        for (int j = 0; j < 8; j++) acc[i][j] = 0.f;

    float ar[8], br[8];
    int T = K >> 4;

    ldA8(Ap, 0, ar);
    ldB8(W, N, bkr, bcolg, bfull, br);
    {
#pragma unroll
        for (int j = 0; j < 8; j++) As[0][akc + j][arow] = ar[j];
        *(float4*)&Bs[0][bkr][bcol]     = make_float4(br[0], br[1], br[2], br[3]);
        *(float4*)&Bs[0][bkr][bcol + 4] = make_float4(br[4], br[5], br[6], br[7]);
    }
    __syncthreads();

    int buf = 0;
    for (int t = 0; t < T; t++) {
        if (t + 1 < T) {
            ldA8(Ap, (t + 1) * 16, ar);
            ldB8(W, N, (t + 1) * 16 + bkr, bcolg, bfull, br);
        }
#pragma unroll
        for (int kk = 0; kk < 16; kk++) {
            float4 a0 = *(const float4*)&As[buf][kk][ty * 4];
            float4 a1 = *(const float4*)&As[buf][kk][ty * 4 + 64];
            float4 b0 = *(const float4*)&Bs[buf][kk][tx * 4];
            float4 b1 = *(const float4*)&Bs[buf][kk][tx * 4 + 64];
            float a[8] = {a0.x, a0.y, a0.z, a0.w, a1.x, a1.y, a1.z, a1.w};
            float b[8] = {b0.x, b0.y, b0.z, b0.w, b1.x, b1.y, b1.z, b1.w};
#pragma unroll
            for (int i = 0; i < 8; i++)
#pragma unroll
                for (int j = 0; j < 8; j++) acc[i][j] = fmaf(a[i], b[j], acc[i][j]);
        }
        if (t + 1 < T) {
            int nb = buf ^ 1;
#pragma unroll
            for (int j = 0; j < 8; j++) As[nb][akc + j][arow] = ar[j];
            *(float4*)&Bs[nb][bkr][bcol]     = make_float4(br[0], br[1], br[2], br[3]);
            *(float4*)&Bs[nb][bkr][bcol + 4] = make_float4(br[4], br[5], br[6], br[7]);
            __syncthreads();
            buf = nb;
        }
    }

#pragma unroll
    for (int i = 0; i < 8; i++) {
        int r = row0 + ty * 4 + (i & 3) + (i >> 2) * 64;
#pragma unroll
        for (int j = 0; j < 8; j++) {
            int c = col0 + tx * 4 + (j & 3) + (j >> 2) * 64;
            if (c < N) {
                float v = acc[i][j] + bias[c];
                if (relu) v = fmaxf(v, 0.f);
                C[(size_t)r * N + c] = v;
            }
        }
    }
}

// ---------------- attention part 1: scores (lower-tri tiles) ----------------
__global__ __launch_bounds__(256)
void score_kernel(const float* __restrict__ Q, const float* __restrict__ Kp,
                  float* __restrict__ S)
{
    int bx = blockIdx.x, by = blockIdx.y;
    if (bx > by) return;                 // fully masked tile
    int z = blockIdx.z;
    int b = z >> 3, h = z & 7;
    __shared__ float Qs[64][68];         // [d][q]
    __shared__ float Ks[64][68];         // [d][k]
    int tid = threadIdx.x;
    const float* Qbase = Q  + ((size_t)(b * Sq + by * 64)) * Dm + h * DK;
    const float* Kbase = Kp + ((size_t)(b * Sq + bx * 64)) * Dm + h * DK;
#pragma unroll
    for (int l = 0; l < 4; l++) {
        int idx = tid + l * 256;
        int r = idx >> 4, c4 = (idx & 15) * 4;
        float4 q4 = *(const float4*)(Qbase + (size_t)r * Dm + c4);
        Qs[c4 + 0][r] = q4.x; Qs[c4 + 1][r] = q4.y;
        Qs[c4 + 2][r] = q4.z; Qs[c4 + 3][r] = q4.w;
        float4 k4 = *(const float4*)(Kbase + (size_t)r * Dm + c4);
        Ks[c4 + 0][r] = k4.x; Ks[c4 + 1][r] = k4.y;
        Ks[c4 + 2][r] = k4.z; Ks[c4 + 3][r] = k4.w;
    }
    __syncthreads();
    int tx = tid & 15, ty = tid >> 4;
    float acc[4][4];
#pragma unroll
    for (int i = 0; i < 4; i++)
#pragma unroll
        for (int j = 0; j < 4; j++) acc[i][j] = 0.f;
#pragma unroll 8
    for (int d = 0; d < 64; d++) {
        float4 a4 = *(const float4*)&Qs[d][ty * 4];
        float4 b4 = *(const float4*)&Ks[d][tx * 4];
        float a[4] = {a4.x, a4.y, a4.z, a4.w};
        float b[4] = {b4.x, b4.y, b4.z, b4.w};
#pragma unroll
        for (int i = 0; i < 4; i++)
#pragma unroll
            for (int j = 0; j < 4; j++) acc[i][j] = fmaf(a[i], b[j], acc[i][j]);
    }
    float* Srow = S + ((size_t)z * Sq + by * 64) * Sq + bx * 64;
#pragma unroll
    for (int i = 0; i < 4; i++)
#pragma unroll
        for (int j = 0; j < 4; j++)
            Srow[(size_t)(ty * 4 + i) * Sq + tx * 4 + j] = acc[i][j] * 0.125f;
}

// ---------------- block reduce helpers (256 threads) ----------------
__device__ __forceinline__ float brmax(float v, float* red) {
    int tid = threadIdx.x;
    red[tid] = v; __syncthreads();
#pragma unroll
    for (int s = 128; s > 0; s >>= 1) {
        if (tid < s) red[tid] = fmaxf(red[tid], red[tid + s]);
        __syncthreads();
    }
    float r = red[0]; __syncthreads(); return r;
}
__device__ __forceinline__ float brsum(float v, float* red) {
    int tid = threadIdx.x;
    red[tid] = v; __syncthreads();
#pragma unroll
    for (int s = 128; s > 0; s >>= 1) {
        if (tid < s) red[tid] += red[tid + s];
        __syncthreads();
    }
    float r = red[0]; __syncthreads(); return r;
}

// ---------------- attention part 2: per-row softmax/cumsum/decay/softmax ------
__global__ __launch_bounds__(256)
void decay_softmax_kernel(float* __restrict__ S, const float* __restrict__ gammas,
                          int layer, int strict)
{
    __shared__ float sc[Sq];
    __shared__ float pa[Sq];
    __shared__ float red[256];
    int i = blockIdx.x, z = blockIdx.y;
    int h = z & 7;
    int tid = threadIdx.x;
    float* row = S + ((size_t)z * Sq + i) * Sq;
    int kmax = i - strict;
    if (kmax < 0) {
        for (int k = tid; k < Sq; k += 256) row[k] = 0.f;
        return;
    }
    for (int k = tid; k < Sq; k += 256) sc[k] = row[k];
    __syncthreads();

    // softmax #1 -> p
    float lm = -3e38f;
    for (int k = tid; k < Sq; k += 256) if (k <= kmax) lm = fmaxf(lm, sc[k]);
    float m1 = brmax(lm, red);
    float ls = 0.f;
    for (int k = tid; k < Sq; k += 256) {
        float p = (k <= kmax) ? expf(sc[k] - m1) : 0.f;
        pa[k] = p; ls += p;
    }
    float inv1 = 1.f / brsum(ls, red);
    for (int k = tid; k < Sq; k += 256) pa[k] *= inv1;
    __syncthreads();

    // inclusive cumsum of p (Hillis-Steele, 512 elems / 256 threads)
    for (int off = 1; off < Sq; off <<= 1) {
        int i1 = tid + 256;
        float a0 = (tid >= off) ? pa[tid - off] : 0.f;
        float a1 = (i1  >= off) ? pa[i1  - off] : 0.f;
        __syncthreads();
        pa[tid] += a0; pa[i1] += a1;
        __syncthreads();
    }
    float total = pa[Sq - 1];

    float gm = gammas[layer * Hh + h];
    float sp = (gm > 20.f) ? gm : log1pf(expf(gm));
    float gamma = -sp;

    for (int k = tid; k < Sq; k += 256) {
        if (k <= kmax) {
            float suf  = total - pa[k];
            float pos  = (float)(i - k);
            float dist = sqrtf(fmaxf(suf * pos, 0.f));
            float te   = expf(dist * gamma);
            te = fminf(fmaxf(te, 1e-5f), 1e5f);
            sc[k] = sc[k] * te;
        }
    }
    __syncthreads();

    // softmax #2 -> attn weights
    lm = -3e38f;
    for (int k = tid; k < Sq; k += 256) if (k <= kmax) lm = fmaxf(lm, sc[k]);
    float m2 = brmax(lm, red);
    ls = 0.f;
    for (int k = tid; k < Sq; k += 256) {
        float p = (k <= kmax) ? expf(sc[k] - m2) : 0.f;
        pa[k] = p; ls += p;
    }
    float inv2 = 1.f / brsum(ls, red);
    for (int k = tid; k < Sq; k += 256) row[k] = (k <= kmax) ? pa[k] * inv2 : 0.f;
}

// ---------------- attention part 3: O = P @ V ----------------
__global__ __launch_bounds__(256)
void av_kernel(const float* __restrict__ S, const float* __restrict__ V,
               float* __restrict__ O)
{
    int qt = blockIdx.x, z = blockIdx.y;
    int b = z >> 3, h = z & 7;
    __shared__ float Ps[16][68];   // [k][q]
    __shared__ float Vs[16][68];   // [k][d]
    int tid = threadIdx.x, tx = tid & 15, ty = tid >> 4;
    float acc[4][4];
#pragma unroll
    for (int i = 0; i < 4; i++)
#pragma unroll
        for (int j = 0; j < 4; j++) acc[i][j] = 0.f;

    const float* Srow  = S + ((size_t)z * Sq + qt * 64) * Sq;
    const float* Vbase = V + ((size_t)b * Sq) * Dm + h * DK;
    int nkt = qt * 4 + 4;            // P[q][k]=0 for k>q -> skip upper tiles
    for (int kt = 0; kt < nkt; kt++) {
        int k0 = kt * 16;
        {
            int q = tid >> 2, kc = (tid & 3) * 4;
            float4 p4 = *(const float4*)(Srow + (size_t)q * Sq + k0 + kc);
            Ps[kc + 0][q] = p4.x; Ps[kc + 1][q] = p4.y;
            Ps[kc + 2][q] = p4.z; Ps[kc + 3][q] = p4.w;
            int kr = tid >> 4, d4 = (tid & 15) * 4;
            *(float4*)&Vs[kr][d4] = *(const float4*)(Vbase + (size_t)(k0 + kr) * Dm + d4);
        }
        __syncthreads();
#pragma unroll
        for (int kk = 0; kk < 16; kk++) {
            float4 a4 = *(const float4*)&Ps[kk][ty * 4];
            float4 b4 = *(const float4*)&Vs[kk][tx * 4];
            float a[4] = {a4.x, a4.y, a4.z, a4.w};
            float b[4] = {b4.x, b4.y, b4.z, b4.w};
#pragma unroll
            for (int i = 0; i < 4; i++)
#pragma unroll
                for (int j = 0; j < 4; j++) acc[i][j] = fmaf(a[i], b[j], acc[i][j]);
        }
        __syncthreads();
    }
    float* Orow = O + ((size_t)(b * Sq + qt * 64)) * Dm + h * DK;
#pragma unroll
    for (int i = 0; i < 4; i++)
#pragma unroll
        for (int j = 0; j < 4; j++)
            Orow[(size_t)(ty * 4 + i) * Dm + tx * 4 + j] = acc[i][j];
}

// ---------------- residual + LayerNorm: out = LN(A + B) ----------------
__global__ void ln_add_kernel(const float* __restrict__ A, const float* __restrict__ Bv,
                              const float* __restrict__ sc, const float* __restrict__ bi,
                              float* __restrict__ out)
{
    int r = blockIdx.x, tid = threadIdx.x;
    const float* a  = A  + (size_t)r * Dm;
    const float* bq = Bv + (size_t)r * Dm;
    float v[4];
    float s = 0.f, s2 = 0.f;
#pragma unroll
    for (int j = 0; j < 4; j++) {
        int c = tid + j * 128;
        float t = a[c] + bq[c];
        v[j] = t; s += t; s2 += t * t;
    }
    __shared__ float rs[4], rs2[4];
#pragma unroll
    for (int o = 16; o > 0; o >>= 1) {
        s  += __shfl_down_sync(0xffffffffu, s,  o);
        s2 += __shfl_down_sync(0xffffffffu, s2, o);
    }
    int w = tid >> 5, l = tid & 31;
    if (l == 0) { rs[w] = s; rs2[w] = s2; }
    __syncthreads();
    float ss  = rs[0] + rs[1] + rs[2] + rs[3];
    float ss2 = rs2[0] + rs2[1] + rs2[2] + rs2[3];
    float mean = ss / 512.f;
    float var  = ss2 / 512.f - mean * mean;
    float rstd = rsqrtf(var + 1e-5f);
#pragma unroll
    for (int j = 0; j < 4; j++) {
        int c = tid + j * 128;
        out[(size_t)r * Dm + c] = (v[j] - mean) * rstd * sc[c] + bi[c];
    }
}

// ---------------- concat [x, x0] ----------------
__global__ void concat_kernel(const float* __restrict__ x, const float* __restrict__ x0,
                              float* __restrict__ out)
{
    int r = blockIdx.x;
    for (int j = threadIdx.x; j < 2 * Dm; j += blockDim.x)
        out[(size_t)r * 2 * Dm + j] = (j < Dm) ? x[(size_t)r*Dm + j]
                                               : x0[(size_t)r*Dm + j - Dm];
}

// ---------------- host ----------------
static inline void gemm(const float* A, const float* W, const float* bias,
                        float* C, int M, int N, int K, int relu)
{
    dim3 grid((N + 127) / 128, M / 128);
    gemm128<<<grid, 256>>>(A, W, bias, C, M, N, K, relu);
}

extern "C" void kernel_launch(void* const* d_in, const int* in_sizes, int n_in,
                              void* d_out, int out_size)
{
    const int*   c_data  = (const int*)  d_in[0];
    const int*   ca_data = (const int*)  d_in[1];
    const float* c_emb   = (const float*)d_in[2];
    const float* ca_emb  = (const float*)d_in[3];
    const float* Wk      = (const float*)d_in[4];
    const float* bk      = (const float*)d_in[5];
    const float* Wv      = (const float*)d_in[6];
    const float* bv      = (const float*)d_in[7];
    const float* Wo      = (const float*)d_in[8];
    const float* bo      = (const float*)d_in[9];
    const float* gammas  = (const float*)d_in[10];
    const float* ln1s    = (const float*)d_in[11];
    const float* ln1b    = (const float*)d_in[12];
    const float* W1      = (const float*)d_in[13];
    const float* b1      = (const float*)d_in[14];
    const float* W2      = (const float*)d_in[15];
    const float* b2      = (const float*)d_in[16];
    const float* ln2s    = (const float*)d_in[17];
    const float* ln2b    = (const float*)d_in[18];
    const float* oW0     = (const float*)d_in[19];
    const float* ob0     = (const float*)d_in[20];
    const float* oW1     = (const float*)d_in[21];
    const float* ob1     = (const float*)d_in[22];
    const float* oW2     = (const float*)d_in[23];
    const float* ob2     = (const float*)d_in[24];
    float* out = (float*)d_out;

    float *x0, *y, *x, *Qb, *Kb, *Vb, *Ab, *Ob, *T1, *Hf, *Cc, *M1, *M2, *Sb;
    cudaGetSymbolAddress((void**)&x0, g_x0);
    cudaGetSymbolAddress((void**)&y,  g_y);
    cudaGetSymbolAddress((void**)&x,  g_x);
    cudaGetSymbolAddress((void**)&Qb, g_Q);
    cudaGetSymbolAddress((void**)&Kb, g_K);
    cudaGetSymbolAddress((void**)&Vb, g_V);
    cudaGetSymbolAddress((void**)&Ab, g_A);
    cudaGetSymbolAddress((void**)&Ob, g_O);
    cudaGetSymbolAddress((void**)&T1, g_T1);
    cudaGetSymbolAddress((void**)&Hf, g_Hf);
    cudaGetSymbolAddress((void**)&Cc, g_Cc);
    cudaGetSymbolAddress((void**)&M1, g_M1);
    cudaGetSymbolAddress((void**)&M2, g_M2);
    cudaGetSymbolAddress((void**)&Sb, g_S);

    embed_kernel<<<MTOK, 128>>>(c_data, ca_data, c_emb, ca_emb, x0, y, x);

    for (int li = 0; li < 6; li++) {
        int strict, ap;
        float* qio; const float *kin, *vin;
        if (li < 2)            { strict = 0; ap = 1; qio = y; kin = x0; vin = y; }
        else {
            int j = li - 2;
            if ((j & 1) == 0)  { strict = 0; ap = 0; qio = x; kin = x;  vin = x; }
            else               { strict = 1; ap = 1; qio = x; kin = x;  vin = y; }
        }
        const float* Wk_i = Wk + (size_t)li * Dm * Dm;  const float* bk_i = bk + li * Dm;
        const float* Wv_i = Wv + (size_t)li * Dm * Dm;  const float* bv_i = bv + li * Dm;
        const float* Wo_i = Wo + (size_t)li * Dm * Dm;  const float* bo_i = bo + li * Dm;

        gemm(qio, Wk_i, bk_i, Qb, MTOK, Dm, Dm, 0);
        const float* Kuse;
        if (kin == qio) Kuse = Qb;
        else { gemm(kin, Wk_i, bk_i, Kb, MTOK, Dm, Dm, 0); Kuse = Kb; }
        gemm(vin, Wv_i, bv_i, Vb, MTOK, Dm, Dm, 0);

        score_kernel<<<dim3(8, 8, NBH), 256>>>(Qb, Kuse, Sb);
        decay_softmax_kernel<<<dim3(Sq, NBH), 256>>>(Sb, gammas, li, strict);
        av_kernel<<<dim3(8, NBH), 256>>>(Sb, Vb, Ab);

        gemm(Ab, Wo_i, bo_i, Ob, MTOK, Dm, Dm, 0);
        ln_add_kernel<<<MTOK, 128>>>(qio, Ob, ln1s + li*Dm, ln1b + li*Dm, ap ? T1 : qio);
        if (ap) {
            gemm(T1, W1 + (size_t)li * Dm * FF, b1 + li * FF, Hf, MTOK, FF, Dm, 1);
            gemm(Hf, W2 + (size_t)li * FF * Dm, b2 + li * Dm, Ob, MTOK, Dm, FF, 0);
            ln_add_kernel<<<MTOK, 128>>>(T1, Ob, ln2s + li*Dm, ln2b + li*Dm, qio);
        }
    }

    concat_kernel<<<MTOK, 256>>>(x, x0, Cc);
    gemm(Cc, oW0, ob0, M1, MTOK, 512,  2 * Dm, 1);
    gemm(M1, oW1, ob1, M2, MTOK, 1024, 512,    1);
    gemm(M2, oW2, ob2, out, MTOK, NCPT, 1024,  0);
}